// round 14
// baseline (speedup 1.0000x reference)
#include <cuda_runtime.h>
#include <cuda_fp16.h>

// GraphConvolution SpMM: out = relu(segment_sum(values[e] * kernel[cols[e]], rows[e]) + bias)
// N=50000, NNZ=1.6M, UNITS=64.
// Round 13: single probe from R10 baseline — SpMM processes 2 rows per warp
// (independent interleaved chains, same in-flight gather depth). Scatter back
// at EPT=8 (12 was neutral). Everything else identical to R10 (65.8us).

#define UNITS 64
#define N_CAP 65536
#define SLOTS 80
#define SPILL_CAP 4096

__device__ int    g_count[N_CAP];
__device__ int2   g_bucket[(long long)N_CAP * SLOTS];  // {col, val-bits}
__device__ __half g_khalf[(long long)N_CAP * UNITS];   // fp16 copy of kernel
__device__ int    g_spill_cnt;
__device__ int    g_spill_row[SPILL_CAP];
__device__ int2   g_spill_edge[SPILL_CAP];

// Zero counts + spill counter (dedicated up-front kernel).
__global__ void gc_zero_kernel(int n) {
    int i = blockIdx.x * blockDim.x + threadIdx.x;
    if (i == 0) g_spill_cnt = 0;
    if (i < n) g_count[i] = 0;
}

// Slot-allocating scatter (strided 8 edges/thread) + interleaved fp32->fp16
// kernel-matrix conversion hidden under atomic latency. (R10 form.)
__global__ void gc_scatter_kernel(const int* __restrict__ rows,
                                  const int* __restrict__ cols,
                                  const float* __restrict__ values,
                                  const float* __restrict__ kern,
                                  int nnz, int stride, int quads) {
    int tid = blockIdx.x * blockDim.x + threadIdx.x;

    int r[8], c[8];
    float v[8];
    bool ok[8];
    #pragma unroll
    for (int j = 0; j < 8; j++) {
        int e = tid + j * stride;
        ok[j] = (e < nnz);
        if (ok[j]) {
            r[j] = rows[e];
            c[j] = cols[e];
            v[j] = values[e];
        }
    }

    for (int q = tid; q < quads; q += stride) {
        float4 f = ((const float4*)kern)[q];
        half2 lo = __floats2half2_rn(f.x, f.y);
        half2 hi = __floats2half2_rn(f.z, f.w);
        uint2 packed;
        packed.x = *(unsigned int*)&lo;
        packed.y = *(unsigned int*)&hi;
        ((uint2*)g_khalf)[q] = packed;
    }

    int p[8];
    #pragma unroll
    for (int j = 0; j < 8; j++) {
        if (ok[j]) p[j] = atomicAdd(&g_count[r[j]], 1);
    }
    #pragma unroll
    for (int j = 0; j < 8; j++) {
        if (ok[j]) {
            if (p[j] < SLOTS) {
                g_bucket[(long long)r[j] * SLOTS + p[j]] =
                    make_int2(c[j], __float_as_int(v[j]));
            } else {
                int s = atomicAdd(&g_spill_cnt, 1);
                if (s < SPILL_CAP) {
                    g_spill_row[s]  = r[j];
                    g_spill_edge[s] = make_int2(c[j], __float_as_int(v[j]));
                }
            }
        }
    }
}

// Accumulate one unroll-8 chunk for a row. Returns via accumulators.
__device__ __forceinline__ void gc_chunk8(const int4* bp, int e,
                                          const half2* kh, int lane,
                                          float& ax, float& ay) {
    int4 q[4];
    #pragma unroll
    for (int j = 0; j < 4; j++) q[j] = bp[(e >> 1) + j];
    half2 h[8];
    #pragma unroll
    for (int j = 0; j < 4; j++) {
        h[2 * j]     = kh[(long long)q[j].x * 32 + lane];
        h[2 * j + 1] = kh[(long long)q[j].z * 32 + lane];
    }
    #pragma unroll
    for (int j = 0; j < 4; j++) {
        float2 ka = __half22float2(h[2 * j]);
        float2 kb = __half22float2(h[2 * j + 1]);
        float va = __int_as_float(q[j].y);
        float vb = __int_as_float(q[j].w);
        ax += va * ka.x;  ay += va * ka.y;
        ax += vb * kb.x;  ay += vb * kb.y;
    }
}

// Drain remaining edges (<8) for a row.
__device__ __forceinline__ void gc_tail(const int2* bk, int e, int cnt,
                                        const half2* kh, int lane,
                                        float& ax, float& ay) {
    for (; e < cnt; e++) {
        int2 ed = bk[e];
        float v = __int_as_float(ed.y);
        float2 k = __half22float2(kh[(long long)ed.x * 32 + lane]);
        ax += v * k.x;
        ay += v * k.y;
    }
}

// Two rows per warp: rows (w, w+half) with independent interleaved chains.
// Lane l accumulates units {2l, 2l+1} per row in fp32. Bias+relu fused.
__global__ void gc_spmm_kernel(const float* __restrict__ bias,
                               float* __restrict__ out,
                               int n, int half) {
    int warp = (blockIdx.x * blockDim.x + threadIdx.x) >> 5;
    int lane = threadIdx.x & 31;
    if (warp >= half) return;

    int rowA = warp;
    int rowB = warp + half;
    bool hasB = (rowB < n);

    int cntA = g_count[rowA];
    int cntB = hasB ? g_count[rowB] : 0;
    if (cntA > SLOTS) cntA = SLOTS;
    if (cntB > SLOTS) cntB = SLOTS;

    const int2* bkA = g_bucket + (long long)rowA * SLOTS;
    const int2* bkB = g_bucket + (long long)rowB * SLOTS;
    const int4* bpA = (const int4*)bkA;
    const int4* bpB = (const int4*)bkB;
    const half2* kh = (const half2*)g_khalf;

    float axA = 0.0f, ayA = 0.0f;
    float axB = 0.0f, ayB = 0.0f;

    int eA = 0, eB = 0;
    // Interleaved main: both rows advance 8 edges per iteration.
    #pragma unroll 1
    while (eA + 8 <= cntA && eB + 8 <= cntB) {
        gc_chunk8(bpA, eA, kh, lane, axA, ayA);
        gc_chunk8(bpB, eB, kh, lane, axB, ayB);
        eA += 8;
        eB += 8;
    }
    // Drain row A.
    #pragma unroll 1
    for (; eA + 8 <= cntA; eA += 8) gc_chunk8(bpA, eA, kh, lane, axA, ayA);
    gc_tail(bkA, eA, cntA, kh, lane, axA, ayA);
    // Drain row B.
    #pragma unroll 1
    for (; eB + 8 <= cntB; eB += 8) gc_chunk8(bpB, eB, kh, lane, axB, ayB);
    gc_tail(bkB, eB, cntB, kh, lane, axB, ayB);

    // Spill edges (broadcast reads; spills==0 in practice).
    int spills = g_spill_cnt;
    if (spills > 0) {
        if (spills > SPILL_CAP) spills = SPILL_CAP;
        for (int s = 0; s < spills; s++) {
            int sr = g_spill_row[s];
            if (sr == rowA || (hasB && sr == rowB)) {
                int2 ed = g_spill_edge[s];
                float v = __int_as_float(ed.y);
                float2 k = __half22float2(kh[(long long)ed.x * 32 + lane]);
                if (sr == rowA) { axA += v * k.x; ayA += v * k.y; }
                else            { axB += v * k.x; ayB += v * k.y; }
            }
        }
    }

    float2 b = ((const float2*)bias)[lane];
    float2 oA;
    oA.x = fmaxf(axA + b.x, 0.0f);
    oA.y = fmaxf(ayA + b.y, 0.0f);
    ((float2*)out)[(long long)rowA * 32 + lane] = oA;
    if (hasB) {
        float2 oB;
        oB.x = fmaxf(axB + b.x, 0.0f);
        oB.y = fmaxf(ayB + b.y, 0.0f);
        ((float2*)out)[(long long)rowB * 32 + lane] = oB;
    }
}

extern "C" void kernel_launch(void* const* d_in, const int* in_sizes, int n_in,
                              void* d_out, int out_size) {
    const int*   rows   = (const int*)d_in[0];
    const int*   cols   = (const int*)d_in[1];
    const float* values = (const float*)d_in[2];
    const float* kern   = (const float*)d_in[3];
    const float* bias   = (const float*)d_in[4];
    float* out = (float*)d_out;

    int nnz = in_sizes[0];
    int n   = out_size / UNITS;

    const int T = 256;

    gc_zero_kernel<<<(n + T - 1) / T, T>>>(n);

    int sthreads = (nnz + 7) / 8;
    int sblocks  = (sthreads + T - 1) / T;
    int quads    = n * (UNITS / 4);
    gc_scatter_kernel<<<sblocks, T>>>(rows, cols, values, kern,
                                      nnz, sblocks * T, quads);

    int half   = (n + 1) / 2;                 // warps needed (2 rows each)
    int blocks = (half * 32 + T - 1) / T;
    gc_spmm_kernel<<<blocks, T>>>(bias, out, n, half);
}

// round 15
// speedup vs baseline: 1.0855x; 1.0855x over previous
#include <cuda_runtime.h>
#include <cuda_fp16.h>

// GraphConvolution SpMM: out = relu(segment_sum(values[e] * kernel[cols[e]], rows[e]) + bias)
// N=50000, NNZ=1.6M, UNITS=64.
// Round 14: single probe from R10 baseline — vectorized grid-stride zero
// kernel (int4 stores, 64 blocks). Scatter + SpMM byte-identical to R10.

#define UNITS 64
#define N_CAP 65536
#define SLOTS 80
#define SPILL_CAP 4096

__device__ int    g_count[N_CAP];
__device__ int2   g_bucket[(long long)N_CAP * SLOTS];  // {col, val-bits}
__device__ __half g_khalf[(long long)N_CAP * UNITS];   // fp16 copy of kernel
__device__ int    g_spill_cnt;
__device__ int    g_spill_row[SPILL_CAP];
__device__ int2   g_spill_edge[SPILL_CAP];

// Zero counts + spill counter: grid-stride int4 stores (wide, few blocks).
__global__ void gc_zero_kernel(int n4) {     // n4 = ceil(n/4) int4 elements
    int tid = blockIdx.x * blockDim.x + threadIdx.x;
    if (tid == 0) g_spill_cnt = 0;
    int step = gridDim.x * blockDim.x;
    int4 z = make_int4(0, 0, 0, 0);
    for (int i = tid; i < n4; i += step) {
        ((int4*)g_count)[i] = z;
    }
}

// Slot-allocating scatter (strided 8 edges/thread) + interleaved fp32->fp16
// kernel-matrix conversion hidden under atomic latency. (R10 form.)
__global__ void gc_scatter_kernel(const int* __restrict__ rows,
                                  const int* __restrict__ cols,
                                  const float* __restrict__ values,
                                  const float* __restrict__ kern,
                                  int nnz, int stride, int quads) {
    int tid = blockIdx.x * blockDim.x + threadIdx.x;

    // Edge front-end: strided, 8 per thread.
    int r[8], c[8];
    float v[8];
    bool ok[8];
    #pragma unroll
    for (int j = 0; j < 8; j++) {
        int e = tid + j * stride;
        ok[j] = (e < nnz);
        if (ok[j]) {
            r[j] = rows[e];
            c[j] = cols[e];
            v[j] = values[e];
        }
    }

    // Conversion work: independent of the edge chain; overlaps atomics below.
    int nthreads = stride;   // stride == gridDim.x * blockDim.x
    for (int q = tid; q < quads; q += nthreads) {
        float4 f = ((const float4*)kern)[q];
        half2 lo = __floats2half2_rn(f.x, f.y);
        half2 hi = __floats2half2_rn(f.z, f.w);
        uint2 packed;
        packed.x = *(unsigned int*)&lo;
        packed.y = *(unsigned int*)&hi;
        ((uint2*)g_khalf)[q] = packed;
    }

    int p[8];
    #pragma unroll
    for (int j = 0; j < 8; j++) {
        if (ok[j]) p[j] = atomicAdd(&g_count[r[j]], 1);
    }
    #pragma unroll
    for (int j = 0; j < 8; j++) {
        if (ok[j]) {
            if (p[j] < SLOTS) {
                g_bucket[(long long)r[j] * SLOTS + p[j]] =
                    make_int2(c[j], __float_as_int(v[j]));
            } else {
                int s = atomicAdd(&g_spill_cnt, 1);
                if (s < SPILL_CAP) {
                    g_spill_row[s]  = r[j];
                    g_spill_edge[s] = make_int2(c[j], __float_as_int(v[j]));
                }
            }
        }
    }
}

// One warp per row; lane l accumulates units {2l, 2l+1} in fp32, gathering
// half2 (4B/lane = 128B/warp per edge). Unroll 16 main loop, unroll 4 mid,
// scalar tail. Spill edges handled inline; bias+relu fused. (R10 form.)
__global__ void gc_spmm_kernel(const float* __restrict__ bias,
                               float* __restrict__ out,
                               int n) {
    int warp = (blockIdx.x * blockDim.x + threadIdx.x) >> 5;
    int lane = threadIdx.x & 31;
    if (warp >= n) return;

    int cnt = g_count[warp];
    if (cnt > SLOTS) cnt = SLOTS;

    const int2* bk = g_bucket + (long long)warp * SLOTS;
    const int4* bp = (const int4*)bk;            // 2 edges per int4
    const half2* kh = (const half2*)g_khalf;     // [row*32 + lane]

    float ax = 0.0f, ay = 0.0f;
    int e = 0;

    #pragma unroll 1
    for (; e + 16 <= cnt; e += 16) {
        int4 q[8];
        #pragma unroll
        for (int j = 0; j < 8; j++) q[j] = bp[(e >> 1) + j];
        half2 h[16];
        #pragma unroll
        for (int j = 0; j < 8; j++) {
            h[2 * j]     = kh[(long long)q[j].x * 32 + lane];
            h[2 * j + 1] = kh[(long long)q[j].z * 32 + lane];
        }
        #pragma unroll
        for (int j = 0; j < 8; j++) {
            float2 ka = __half22float2(h[2 * j]);
            float2 kb = __half22float2(h[2 * j + 1]);
            float va = __int_as_float(q[j].y);
            float vb = __int_as_float(q[j].w);
            ax += va * ka.x;  ay += va * ka.y;
            ax += vb * kb.x;  ay += vb * kb.y;
        }
    }
    #pragma unroll 1
    for (; e + 4 <= cnt; e += 4) {
        int4 q0 = bp[(e >> 1) + 0];
        int4 q1 = bp[(e >> 1) + 1];
        half2 h0 = kh[(long long)q0.x * 32 + lane];
        half2 h1 = kh[(long long)q0.z * 32 + lane];
        half2 h2 = kh[(long long)q1.x * 32 + lane];
        half2 h3 = kh[(long long)q1.z * 32 + lane];
        float2 k0 = __half22float2(h0);
        float2 k1 = __half22float2(h1);
        float2 k2 = __half22float2(h2);
        float2 k3 = __half22float2(h3);
        float v0 = __int_as_float(q0.y), v1 = __int_as_float(q0.w);
        float v2 = __int_as_float(q1.y), v3 = __int_as_float(q1.w);
        ax += v0 * k0.x;  ay += v0 * k0.y;
        ax += v1 * k1.x;  ay += v1 * k1.y;
        ax += v2 * k2.x;  ay += v2 * k2.y;
        ax += v3 * k3.x;  ay += v3 * k3.y;
    }
    for (; e < cnt; e++) {
        int2 ed = bk[e];
        float v = __int_as_float(ed.y);
        float2 k = __half22float2(kh[(long long)ed.x * 32 + lane]);
        ax += v * k.x;
        ay += v * k.y;
    }

    // Spill edges for this row (broadcast reads; spills==0 in practice).
    int spills = g_spill_cnt;
    if (spills > 0) {
        if (spills > SPILL_CAP) spills = SPILL_CAP;
        for (int s = 0; s < spills; s++) {
            if (g_spill_row[s] == warp) {
                int2 ed = g_spill_edge[s];
                float v = __int_as_float(ed.y);
                float2 k = __half22float2(kh[(long long)ed.x * 32 + lane]);
                ax += v * k.x;
                ay += v * k.y;
            }
        }
    }

    float2 b = ((const float2*)bias)[lane];
    float2 o;
    o.x = fmaxf(ax + b.x, 0.0f);
    o.y = fmaxf(ay + b.y, 0.0f);
    ((float2*)out)[(long long)warp * 32 + lane] = o;
}

extern "C" void kernel_launch(void* const* d_in, const int* in_sizes, int n_in,
                              void* d_out, int out_size) {
    const int*   rows   = (const int*)d_in[0];
    const int*   cols   = (const int*)d_in[1];
    const float* values = (const float*)d_in[2];
    const float* kern   = (const float*)d_in[3];
    const float* bias   = (const float*)d_in[4];
    float* out = (float*)d_out;

    int nnz = in_sizes[0];
    int n   = out_size / UNITS;

    const int T = 256;

    int n4 = (n + 3) / 4;                        // int4 elements to zero
    gc_zero_kernel<<<64, T>>>(n4);

    int sthreads = (nnz + 7) / 8;
    int sblocks  = (sthreads + T - 1) / T;
    int quads    = n * (UNITS / 4);              // float4 elements of kernel matrix
    gc_scatter_kernel<<<sblocks, T>>>(rows, cols, values, kern,
                                      nnz, sblocks * T, quads);

    int blocks = (n * 32 + T - 1) / T;
    gc_spmm_kernel<<<blocks, T>>>(bias, out, n);
}

// round 16
// speedup vs baseline: 1.2015x; 1.1069x over previous
#include <cuda_runtime.h>
#include <cuda_fp16.h>

// GraphConvolution SpMM: out = relu(segment_sum(values[e] * kernel[cols[e]], rows[e]) + bias)
// N=50000, NNZ=1.6M, UNITS=64.
// Round 15: 4-byte packed edges (col:16 | val-fp16:16). Halves bucket
// footprint (40->20MB), scatter store width, and SpMM edge-read bytes;
// SpMM reads 4 edges per uint4. Spill path keeps fp32 values.

#define UNITS 64
#define N_CAP 65536
#define SLOTS 80
#define SPILL_CAP 4096

__device__ int      g_count[N_CAP];
__device__ unsigned g_bucket[(long long)N_CAP * SLOTS]; // col | (val_h<<16)
__device__ __half   g_khalf[(long long)N_CAP * UNITS];  // fp16 copy of kernel
__device__ int      g_spill_cnt;
__device__ int      g_spill_row[SPILL_CAP];
__device__ int2     g_spill_edge[SPILL_CAP];            // {col, fp32 val bits}

// Zero counts + spill counter: grid-stride int4 stores.
__global__ void gc_zero_kernel(int n4) {
    int tid = blockIdx.x * blockDim.x + threadIdx.x;
    if (tid == 0) g_spill_cnt = 0;
    int step = gridDim.x * blockDim.x;
    int4 z = make_int4(0, 0, 0, 0);
    for (int i = tid; i < n4; i += step) {
        ((int4*)g_count)[i] = z;
    }
}

// Slot-allocating scatter (strided 8 edges/thread) + interleaved fp32->fp16
// kernel-matrix conversion hidden under atomic latency. Packed 4B stores.
__global__ void gc_scatter_kernel(const int* __restrict__ rows,
                                  const int* __restrict__ cols,
                                  const float* __restrict__ values,
                                  const float* __restrict__ kern,
                                  int nnz, int stride, int quads) {
    int tid = blockIdx.x * blockDim.x + threadIdx.x;

    int r[8], c[8];
    float v[8];
    bool ok[8];
    #pragma unroll
    for (int j = 0; j < 8; j++) {
        int e = tid + j * stride;
        ok[j] = (e < nnz);
        if (ok[j]) {
            r[j] = rows[e];
            c[j] = cols[e];
            v[j] = values[e];
        }
    }

    // Conversion work: independent of the edge chain; overlaps atomics below.
    for (int q = tid; q < quads; q += stride) {
        float4 f = ((const float4*)kern)[q];
        half2 lo = __floats2half2_rn(f.x, f.y);
        half2 hi = __floats2half2_rn(f.z, f.w);
        uint2 packed;
        packed.x = *(unsigned int*)&lo;
        packed.y = *(unsigned int*)&hi;
        ((uint2*)g_khalf)[q] = packed;
    }

    int p[8];
    #pragma unroll
    for (int j = 0; j < 8; j++) {
        if (ok[j]) p[j] = atomicAdd(&g_count[r[j]], 1);
    }
    #pragma unroll
    for (int j = 0; j < 8; j++) {
        if (ok[j]) {
            if (p[j] < SLOTS) {
                unsigned vh = (unsigned)__half_as_ushort(__float2half_rn(v[j]));
                unsigned pk = ((unsigned)c[j] & 0xFFFFu) | (vh << 16);
                g_bucket[(long long)r[j] * SLOTS + p[j]] = pk;
            } else {
                int s = atomicAdd(&g_spill_cnt, 1);
                if (s < SPILL_CAP) {
                    g_spill_row[s]  = r[j];
                    g_spill_edge[s] = make_int2(c[j], __float_as_int(v[j]));
                }
            }
        }
    }
}

// One warp per row; lane l accumulates units {2l, 2l+1} in fp32, gathering
// half2 (4B/lane = 128B/warp per edge). 4 packed edges per uint4 broadcast
// load; unroll-16 main, unroll-4 mid, scalar tail. Bias+relu fused.
__global__ void gc_spmm_kernel(const float* __restrict__ bias,
                               float* __restrict__ out,
                               int n) {
    int warp = (blockIdx.x * blockDim.x + threadIdx.x) >> 5;
    int lane = threadIdx.x & 31;
    if (warp >= n) return;

    int cnt = g_count[warp];
    if (cnt > SLOTS) cnt = SLOTS;

    const unsigned* bk = g_bucket + (long long)warp * SLOTS;
    const uint4* bq = (const uint4*)bk;          // 4 edges per uint4 (320B-aligned base)
    const half2* kh = (const half2*)g_khalf;     // [row*32 + lane]

    float ax = 0.0f, ay = 0.0f;
    int e = 0;

    #pragma unroll 1
    for (; e + 16 <= cnt; e += 16) {
        uint4 q[4];
        #pragma unroll
        for (int j = 0; j < 4; j++) q[j] = bq[(e >> 2) + j];
        unsigned pk[16];
        #pragma unroll
        for (int j = 0; j < 4; j++) {
            pk[4 * j + 0] = q[j].x;
            pk[4 * j + 1] = q[j].y;
            pk[4 * j + 2] = q[j].z;
            pk[4 * j + 3] = q[j].w;
        }
        half2 h[16];
        #pragma unroll
        for (int j = 0; j < 16; j++) {
            h[j] = kh[(long long)(pk[j] & 0xFFFFu) * 32 + lane];
        }
        #pragma unroll
        for (int j = 0; j < 16; j++) {
            float2 k = __half22float2(h[j]);
            float v = __half2float(__ushort_as_half((unsigned short)(pk[j] >> 16)));
            ax += v * k.x;
            ay += v * k.y;
        }
    }
    #pragma unroll 1
    for (; e + 4 <= cnt; e += 4) {
        uint4 q = bq[e >> 2];
        half2 h0 = kh[(long long)(q.x & 0xFFFFu) * 32 + lane];
        half2 h1 = kh[(long long)(q.y & 0xFFFFu) * 32 + lane];
        half2 h2 = kh[(long long)(q.z & 0xFFFFu) * 32 + lane];
        half2 h3 = kh[(long long)(q.w & 0xFFFFu) * 32 + lane];
        float2 k0 = __half22float2(h0);
        float2 k1 = __half22float2(h1);
        float2 k2 = __half22float2(h2);
        float2 k3 = __half22float2(h3);
        float v0 = __half2float(__ushort_as_half((unsigned short)(q.x >> 16)));
        float v1 = __half2float(__ushort_as_half((unsigned short)(q.y >> 16)));
        float v2 = __half2float(__ushort_as_half((unsigned short)(q.z >> 16)));
        float v3 = __half2float(__ushort_as_half((unsigned short)(q.w >> 16)));
        ax += v0 * k0.x;  ay += v0 * k0.y;
        ax += v1 * k1.x;  ay += v1 * k1.y;
        ax += v2 * k2.x;  ay += v2 * k2.y;
        ax += v3 * k3.x;  ay += v3 * k3.y;
    }
    for (; e < cnt; e++) {
        unsigned pk = bk[e];
        float v = __half2float(__ushort_as_half((unsigned short)(pk >> 16)));
        float2 k = __half22float2(kh[(long long)(pk & 0xFFFFu) * 32 + lane]);
        ax += v * k.x;
        ay += v * k.y;
    }

    // Spill edges for this row (broadcast reads; spills==0 in practice).
    int spills = g_spill_cnt;
    if (spills > 0) {
        if (spills > SPILL_CAP) spills = SPILL_CAP;
        for (int s = 0; s < spills; s++) {
            if (g_spill_row[s] == warp) {
                int2 ed = g_spill_edge[s];
                float v = __int_as_float(ed.y);
                float2 k = __half22float2(kh[(long long)ed.x * 32 + lane]);
                ax += v * k.x;
                ay += v * k.y;
            }
        }
    }

    float2 b = ((const float2*)bias)[lane];
    float2 o;
    o.x = fmaxf(ax + b.x, 0.0f);
    o.y = fmaxf(ay + b.y, 0.0f);
    ((float2*)out)[(long long)warp * 32 + lane] = o;
}

extern "C" void kernel_launch(void* const* d_in, const int* in_sizes, int n_in,
                              void* d_out, int out_size) {
    const int*   rows   = (const int*)d_in[0];
    const int*   cols   = (const int*)d_in[1];
    const float* values = (const float*)d_in[2];
    const float* kern   = (const float*)d_in[3];
    const float* bias   = (const float*)d_in[4];
    float* out = (float*)d_out;

    int nnz = in_sizes[0];
    int n   = out_size / UNITS;

    const int T = 256;

    int n4 = (n + 3) / 4;
    gc_zero_kernel<<<64, T>>>(n4);

    int sthreads = (nnz + 7) / 8;
    int sblocks  = (sthreads + T - 1) / T;
    int quads    = n * (UNITS / 4);
    gc_scatter_kernel<<<sblocks, T>>>(rows, cols, values, kern,
                                      nnz, sblocks * T, quads);

    int blocks = (n * 32 + T - 1) / T;
    gc_spmm_kernel<<<blocks, T>>>(bias, out, n);
}